// round 8
// baseline (speedup 1.0000x reference)
#include <cuda_runtime.h>

#define D_DIM 64
#define H_DIM 256
#define W_DIM 256
#define PLANE (H_DIM * W_DIM)
#define D_CHUNK 8   // outputs per block along D (4 shared pairs)

// compare-exchange: a=min, b=max
__device__ __forceinline__ void s2(float& a, float& b) {
    float t = fminf(a, b);
    b = fmaxf(a, b);
    a = t;
}

// Optimal 9-input sorting network: 25 comparators, depth 7.
__device__ __forceinline__ void sort9(float* v) {
    s2(v[0],v[3]); s2(v[1],v[7]); s2(v[2],v[5]); s2(v[4],v[8]);
    s2(v[0],v[7]); s2(v[2],v[4]); s2(v[3],v[8]); s2(v[5],v[6]);
    s2(v[0],v[2]); s2(v[1],v[3]); s2(v[4],v[5]); s2(v[7],v[8]);
    s2(v[1],v[4]); s2(v[3],v[6]); s2(v[5],v[7]);
    s2(v[0],v[1]); s2(v[2],v[4]); s2(v[3],v[5]); s2(v[6],v[8]);
    s2(v[2],v[3]); s2(v[4],v[5]); s2(v[6],v[7]);
    s2(v[1],v[2]); s2(v[3],v[4]); s2(v[5],v[6]);
}

// ---- Batcher odd-even merges of two sorted arrays ----
__device__ __forceinline__ void merge11(const float* a, const float* b, float* c) {
    c[0] = a[0]; c[1] = b[0]; s2(c[0], c[1]);
}
__device__ __forceinline__ void merge22(const float* a, const float* b, float* c) {
    float ae[1] = {a[0]}, be[1] = {b[0]}, ao[1] = {a[1]}, bo[1] = {b[1]};
    float e[2], o[2];
    merge11(ae, be, e); merge11(ao, bo, o);
    c[0] = e[0];
    c[1] = o[0]; c[2] = e[1]; s2(c[1], c[2]);
    c[3] = o[1];
}
__device__ __forceinline__ void merge33(const float* a, const float* b, float* c) {
    float ae[2] = {a[0], a[2]}, be[2] = {b[0], b[2]};
    float ao[1] = {a[1]},       bo[1] = {b[1]};
    float e[4], o[2];
    merge22(ae, be, e); merge11(ao, bo, o);
    c[0] = e[0];
    c[1] = o[0]; c[2] = e[1]; s2(c[1], c[2]);
    c[3] = o[1]; c[4] = e[2]; s2(c[3], c[4]);
    c[5] = e[3];
}
__device__ __forceinline__ void merge44(const float* a, const float* b, float* c) {
    float ae[2] = {a[0], a[2]}, be[2] = {b[0], b[2]};
    float ao[2] = {a[1], a[3]}, bo[2] = {b[1], b[3]};
    float e[4], o[4];
    merge22(ae, be, e); merge22(ao, bo, o);
    c[0] = e[0];
    c[1] = o[0]; c[2] = e[1]; s2(c[1], c[2]);
    c[3] = o[1]; c[4] = e[2]; s2(c[3], c[4]);
    c[5] = o[2]; c[6] = e[3]; s2(c[5], c[6]);
    c[7] = o[3];
}
__device__ __forceinline__ void merge55(const float* a, const float* b, float* c) {
    float ae[3] = {a[0], a[2], a[4]}, be[3] = {b[0], b[2], b[4]};
    float ao[2] = {a[1], a[3]},       bo[2] = {b[1], b[3]};
    float e[6], o[4];
    merge33(ae, be, e); merge22(ao, bo, o);
    c[0] = e[0];
#pragma unroll
    for (int i = 1; i <= 4; ++i) { c[2*i-1] = o[i-1]; c[2*i] = e[i]; s2(c[2*i-1], c[2*i]); }
    c[9] = e[5];
}
// Full merge of two sorted 9s into sorted 18; only c[4..13] are consumed,
// comparators feeding only the ends are dead-coded by ptxas.
__device__ __forceinline__ void merge99(const float* a, const float* b, float* c) {
    float ae[5] = {a[0], a[2], a[4], a[6], a[8]};
    float be[5] = {b[0], b[2], b[4], b[6], b[8]};
    float ao[4] = {a[1], a[3], a[5], a[7]};
    float bo[4] = {b[1], b[3], b[5], b[7]};
    float e[10], o[8];
    merge55(ae, be, e); merge44(ao, bo, o);
    c[0] = e[0];
#pragma unroll
    for (int i = 1; i <= 8; ++i) { c[2*i-1] = o[i-1]; c[2*i] = e[i]; s2(c[2*i-1], c[2*i]); }
    c[17] = e[9];
}

// 10th smallest of sorted X[0..8] ∪ sorted T[0..9]  (== median of the 27-window).
// Closed form: max( T[0], max_i min(X[i], T[9-i]) ).
__device__ __forceinline__ float select10(const float* X, const float* T) {
    float c0 = T[0];
    float c1 = fminf(X[0], T[9]);
    float c2 = fminf(X[1], T[8]);
    float c3 = fminf(X[2], T[7]);
    float c4 = fminf(X[3], T[6]);
    float c5 = fminf(X[4], T[5]);
    float c6 = fminf(X[5], T[4]);
    float c7 = fminf(X[6], T[3]);
    float c8 = fminf(X[7], T[2]);
    float c9 = fminf(X[8], T[1]);
    float m01 = fmaxf(c0, c1), m23 = fmaxf(c2, c3);
    float m45 = fmaxf(c4, c5), m67 = fmaxf(c6, c7);
    float m89 = fmaxf(c8, c9);
    return fmaxf(fmaxf(fmaxf(m01, m23), fmaxf(m45, m67)), m89);
}

__global__ void __launch_bounds__(256, 4)
median3d_kernel(const float* __restrict__ x, float* __restrict__ y) {
    const int w = threadIdx.x;          // 0..255
    const int h = blockIdx.x;           // 0..255
    const int d0 = blockIdx.y * D_CHUNK;

    // Clamped neighbor offsets (always-legal addresses) + fp masks for exact
    // zero padding. Masks ride the lightly-used fma pipe (FMUL), replacing
    // predicate/SEL traffic on the saturated alu pipe. Inputs are finite, so
    // v * 0.0f == 0.0f exactly.
    const int ohm = (h > 0)         ? -W_DIM : 0;
    const int ohp = (h < H_DIM - 1) ?  W_DIM : 0;
    const int owm = (w > 0)         ? -1     : 0;
    const int owp = (w < W_DIM - 1) ?  1     : 0;
    const float fhm = (h > 0)         ? 1.0f : 0.0f;
    const float fhp = (h < H_DIM - 1) ? 1.0f : 0.0f;
    const float fwm = (w > 0)         ? 1.0f : 0.0f;
    const float fwp = (w < W_DIM - 1) ? 1.0f : 0.0f;
    const float m00 = fhm * fwm, m01 = fhm, m02 = fhm * fwp;
    const float m10 = fwm,                   m12 = fwp;
    const float m20 = fhp * fwm, m21 = fhp, m22 = fhp * fwp;

    const float* p0 = x + (size_t)h * W_DIM + w;
    float* o0 = y + (size_t)h * W_DIM + w;

    // raw masked 9-neighborhood load of plane k (k always valid here)
#define LOADRAW(P, k)                                                   \
    do {                                                                \
        const float* q = p0 + (size_t)(k) * PLANE;                      \
        P[0] = __ldg(q + ohm + owm) * m00;                              \
        P[1] = __ldg(q + ohm)       * m01;                              \
        P[2] = __ldg(q + ohm + owp) * m02;                              \
        P[3] = __ldg(q + owm)       * m10;                              \
        P[4] = __ldg(q);                                                \
        P[5] = __ldg(q + owp)       * m12;                              \
        P[6] = __ldg(q + ohp + owm) * m20;                              \
        P[7] = __ldg(q + ohp)       * m21;                              \
        P[8] = __ldg(q + ohp + owp) * m22;                              \
    } while (0)

    float Pm[9], P0[9], P1[9], P2[9];   // sorted planes d-1, d, d+1, d+2
    float c[18];

    // plane d0-1 (zero pad if d0 == 0)
    if (d0 == 0) {
#pragma unroll
        for (int i = 0; i < 9; ++i) Pm[i] = 0.0f;
    } else {
        LOADRAW(Pm, d0 - 1);
        sort9(Pm);
    }
    // plane d0
    LOADRAW(P0, d0);
    sort9(P0);

#pragma unroll
    for (int pp = 0; pp < D_CHUNK / 2; ++pp) {
        const int d = d0 + 2 * pp;      // pair (d, d+1); d <= 62

        // issue BOTH planes' 18 loads up front (MLP), then both sorts (ILP)
        LOADRAW(P1, d + 1);             // always exists (d+1 <= 63)
        const bool have2 = (d + 2 < D_DIM);
        if (have2) {
            LOADRAW(P2, d + 2);
        } else {
#pragma unroll
            for (int i = 0; i < 9; ++i) P2[i] = 0.0f;   // plane 64 = zero pad
        }

        sort9(P1);
        if (have2) sort9(P2);           // zeros already sorted

        // shared sorted merge of planes (d, d+1); middle 10 = c[4..13]
        merge99(P0, P1, c);

        // two independent rank selections (high ILP)
        o0[(size_t)d * PLANE]       = select10(Pm, c + 4);
        o0[(size_t)(d + 1) * PLANE] = select10(P2, c + 4);

        // slide by 2 (register-renamed under full unroll)
#pragma unroll
        for (int i = 0; i < 9; ++i) { Pm[i] = P1[i]; P0[i] = P2[i]; }
    }
#undef LOADRAW
}

extern "C" void kernel_launch(void* const* d_in, const int* in_sizes, int n_in,
                              void* d_out, int out_size) {
    const float* x = (const float*)d_in[0];
    float* y = (float*)d_out;
    dim3 block(256, 1, 1);
    dim3 grid(H_DIM, D_DIM / D_CHUNK, 1);  // (256, 8) = 2048 CTAs
    median3d_kernel<<<grid, block>>>(x, y);
}

// round 9
// speedup vs baseline: 1.1220x; 1.1220x over previous
#include <cuda_runtime.h>

#define D_DIM 64
#define H_DIM 256
#define W_DIM 256
#define PLANE (H_DIM * W_DIM)
#define D_CHUNK 8   // outputs per block along D (4 shared pairs)

// compare-exchange: a=min, b=max
__device__ __forceinline__ void s2(float& a, float& b) {
    float t = fminf(a, b);
    b = fmaxf(a, b);
    a = t;
}

// Optimal 9-input sorting network: 25 comparators, depth 7.
__device__ __forceinline__ void sort9(float* v) {
    s2(v[0],v[3]); s2(v[1],v[7]); s2(v[2],v[5]); s2(v[4],v[8]);
    s2(v[0],v[7]); s2(v[2],v[4]); s2(v[3],v[8]); s2(v[5],v[6]);
    s2(v[0],v[2]); s2(v[1],v[3]); s2(v[4],v[5]); s2(v[7],v[8]);
    s2(v[1],v[4]); s2(v[3],v[6]); s2(v[5],v[7]);
    s2(v[0],v[1]); s2(v[2],v[4]); s2(v[3],v[5]); s2(v[6],v[8]);
    s2(v[2],v[3]); s2(v[4],v[5]); s2(v[6],v[7]);
    s2(v[1],v[2]); s2(v[3],v[4]); s2(v[5],v[6]);
}

// ---- Batcher odd-even merges of two sorted arrays ----
__device__ __forceinline__ void merge11(const float* a, const float* b, float* c) {
    c[0] = a[0]; c[1] = b[0]; s2(c[0], c[1]);
}
__device__ __forceinline__ void merge22(const float* a, const float* b, float* c) {
    float ae[1] = {a[0]}, be[1] = {b[0]}, ao[1] = {a[1]}, bo[1] = {b[1]};
    float e[2], o[2];
    merge11(ae, be, e); merge11(ao, bo, o);
    c[0] = e[0];
    c[1] = o[0]; c[2] = e[1]; s2(c[1], c[2]);
    c[3] = o[1];
}
__device__ __forceinline__ void merge33(const float* a, const float* b, float* c) {
    float ae[2] = {a[0], a[2]}, be[2] = {b[0], b[2]};
    float ao[1] = {a[1]},       bo[1] = {b[1]};
    float e[4], o[2];
    merge22(ae, be, e); merge11(ao, bo, o);
    c[0] = e[0];
    c[1] = o[0]; c[2] = e[1]; s2(c[1], c[2]);
    c[3] = o[1]; c[4] = e[2]; s2(c[3], c[4]);
    c[5] = e[3];
}
__device__ __forceinline__ void merge44(const float* a, const float* b, float* c) {
    float ae[2] = {a[0], a[2]}, be[2] = {b[0], b[2]};
    float ao[2] = {a[1], a[3]}, bo[2] = {b[1], b[3]};
    float e[4], o[4];
    merge22(ae, be, e); merge22(ao, bo, o);
    c[0] = e[0];
    c[1] = o[0]; c[2] = e[1]; s2(c[1], c[2]);
    c[3] = o[1]; c[4] = e[2]; s2(c[3], c[4]);
    c[5] = o[2]; c[6] = e[3]; s2(c[5], c[6]);
    c[7] = o[3];
}
__device__ __forceinline__ void merge55(const float* a, const float* b, float* c) {
    float ae[3] = {a[0], a[2], a[4]}, be[3] = {b[0], b[2], b[4]};
    float ao[2] = {a[1], a[3]},       bo[2] = {b[1], b[3]};
    float e[6], o[4];
    merge33(ae, be, e); merge22(ao, bo, o);
    c[0] = e[0];
#pragma unroll
    for (int i = 1; i <= 4; ++i) { c[2*i-1] = o[i-1]; c[2*i] = e[i]; s2(c[2*i-1], c[2*i]); }
    c[9] = e[5];
}
// Full merge of two sorted 9s into sorted 18; only c[4..13] are consumed,
// comparators feeding only the ends are dead-coded by ptxas.
__device__ __forceinline__ void merge99(const float* a, const float* b, float* c) {
    float ae[5] = {a[0], a[2], a[4], a[6], a[8]};
    float be[5] = {b[0], b[2], b[4], b[6], b[8]};
    float ao[4] = {a[1], a[3], a[5], a[7]};
    float bo[4] = {b[1], b[3], b[5], b[7]};
    float e[10], o[8];
    merge55(ae, be, e); merge44(ao, bo, o);
    c[0] = e[0];
#pragma unroll
    for (int i = 1; i <= 8; ++i) { c[2*i-1] = o[i-1]; c[2*i] = e[i]; s2(c[2*i-1], c[2*i]); }
    c[17] = e[9];
}

// 10th smallest of sorted X[0..8] ∪ sorted T[0..9]  (== median of the 27-window).
// Closed form: max( T[0], max_i min(X[i], T[9-i]) ).
__device__ __forceinline__ float select10(const float* X, const float* T) {
    float c0 = T[0];
    float c1 = fminf(X[0], T[9]);
    float c2 = fminf(X[1], T[8]);
    float c3 = fminf(X[2], T[7]);
    float c4 = fminf(X[3], T[6]);
    float c5 = fminf(X[4], T[5]);
    float c6 = fminf(X[5], T[4]);
    float c7 = fminf(X[6], T[3]);
    float c8 = fminf(X[7], T[2]);
    float c9 = fminf(X[8], T[1]);
    float m01 = fmaxf(c0, c1), m23 = fmaxf(c2, c3);
    float m45 = fmaxf(c4, c5), m67 = fmaxf(c6, c7);
    float m89 = fmaxf(c8, c9);
    return fmaxf(fmaxf(fmaxf(m01, m23), fmaxf(m45, m67)), m89);
}

// Load the 3x3 (h,w) neighborhood of one D-plane with zero padding.
// Ternary form -> constant immediate LDG offsets + hoisted predicates (R4-proven).
__device__ __forceinline__ void load9(const float* __restrict__ q, float* P,
                                      bool hm, bool hp, bool wm, bool wp) {
    P[0] = (hm && wm) ? __ldg(q - W_DIM - 1) : 0.0f;
    P[1] = (hm)       ? __ldg(q - W_DIM)     : 0.0f;
    P[2] = (hm && wp) ? __ldg(q - W_DIM + 1) : 0.0f;
    P[3] = (wm)       ? __ldg(q - 1)         : 0.0f;
    P[4] =              __ldg(q);
    P[5] = (wp)       ? __ldg(q + 1)         : 0.0f;
    P[6] = (hp && wm) ? __ldg(q + W_DIM - 1) : 0.0f;
    P[7] = (hp)       ? __ldg(q + W_DIM)     : 0.0f;
    P[8] = (hp && wp) ? __ldg(q + W_DIM + 1) : 0.0f;
}

__global__ void __launch_bounds__(128, 9)
median3d_kernel(const float* __restrict__ x, float* __restrict__ y) {
    const int w = blockIdx.x * 128 + threadIdx.x;   // 0..255
    const int h = blockIdx.y;                       // 0..255
    const int d0 = blockIdx.z * D_CHUNK;

    const bool wm = (w > 0), wp = (w < W_DIM - 1);
    const bool hm = (h > 0), hp = (h < H_DIM - 1);

    const float* p0 = x + (size_t)h * W_DIM + w;
    float* o0 = y + (size_t)h * W_DIM + w;

    float Pm[9], P0[9], P1[9], P2[9];   // sorted planes d-1, d, d+1, d+2
    float c[18];

    // plane d0-1 (zero pad if d0 == 0)
    if (d0 == 0) {
#pragma unroll
        for (int i = 0; i < 9; ++i) Pm[i] = 0.0f;
    } else {
        load9(p0 + (size_t)(d0 - 1) * PLANE, Pm, hm, hp, wm, wp);
        sort9(Pm);
    }
    // plane d0
    load9(p0 + (size_t)d0 * PLANE, P0, hm, hp, wm, wp);
    sort9(P0);

#pragma unroll
    for (int pp = 0; pp < D_CHUNK / 2; ++pp) {
        const int d = d0 + 2 * pp;      // pair (d, d+1); d <= 62

        // plane d+1 (always exists) — sorted
        load9(p0 + (size_t)(d + 1) * PLANE, P1, hm, hp, wm, wp);
        sort9(P1);

        // plane d+2 (zero pad if d+2 == D_DIM) — sorted
        if (d + 2 < D_DIM) {
            load9(p0 + (size_t)(d + 2) * PLANE, P2, hm, hp, wm, wp);
            sort9(P2);
        } else {
#pragma unroll
            for (int i = 0; i < 9; ++i) P2[i] = 0.0f;
        }

        // shared sorted merge of planes (d, d+1); middle 10 = c[4..13]
        merge99(P0, P1, c);

        // two independent rank selections (high ILP)
        o0[(size_t)d * PLANE]       = select10(Pm, c + 4);
        o0[(size_t)(d + 1) * PLANE] = select10(P2, c + 4);

        // slide by 2: Pm <- P1, P0 <- P2 (register-renamed under full unroll)
#pragma unroll
        for (int i = 0; i < 9; ++i) { Pm[i] = P1[i]; P0[i] = P2[i]; }
    }
}

extern "C" void kernel_launch(void* const* d_in, const int* in_sizes, int n_in,
                              void* d_out, int out_size) {
    const float* x = (const float*)d_in[0];
    float* y = (float*)d_out;
    dim3 block(128, 1, 1);
    dim3 grid(W_DIM / 128, H_DIM, D_DIM / D_CHUNK);  // (2, 256, 8) = 4096 CTAs
    median3d_kernel<<<grid, block>>>(x, y);
}

// round 10
// speedup vs baseline: 1.1311x; 1.0082x over previous
#include <cuda_runtime.h>

#define D_DIM 64
#define H_DIM 256
#define W_DIM 256
#define PLANE (H_DIM * W_DIM)
#define D_CHUNK 8   // outputs per block along D (4 shared pairs)

// compare-exchange: a=min, b=max
__device__ __forceinline__ void s2(float& a, float& b) {
    float t = fminf(a, b);
    b = fmaxf(a, b);
    a = t;
}

// Optimal 9-input sorting network: 25 comparators, depth 7.
__device__ __forceinline__ void sort9(float* v) {
    s2(v[0],v[3]); s2(v[1],v[7]); s2(v[2],v[5]); s2(v[4],v[8]);
    s2(v[0],v[7]); s2(v[2],v[4]); s2(v[3],v[8]); s2(v[5],v[6]);
    s2(v[0],v[2]); s2(v[1],v[3]); s2(v[4],v[5]); s2(v[7],v[8]);
    s2(v[1],v[4]); s2(v[3],v[6]); s2(v[5],v[7]);
    s2(v[0],v[1]); s2(v[2],v[4]); s2(v[3],v[5]); s2(v[6],v[8]);
    s2(v[2],v[3]); s2(v[4],v[5]); s2(v[6],v[7]);
    s2(v[1],v[2]); s2(v[3],v[4]); s2(v[5],v[6]);
}

// ---- Batcher odd-even merges of two sorted arrays ----
__device__ __forceinline__ void merge11(const float* a, const float* b, float* c) {
    c[0] = a[0]; c[1] = b[0]; s2(c[0], c[1]);
}
__device__ __forceinline__ void merge22(const float* a, const float* b, float* c) {
    float ae[1] = {a[0]}, be[1] = {b[0]}, ao[1] = {a[1]}, bo[1] = {b[1]};
    float e[2], o[2];
    merge11(ae, be, e); merge11(ao, bo, o);
    c[0] = e[0];
    c[1] = o[0]; c[2] = e[1]; s2(c[1], c[2]);
    c[3] = o[1];
}
__device__ __forceinline__ void merge33(const float* a, const float* b, float* c) {
    float ae[2] = {a[0], a[2]}, be[2] = {b[0], b[2]};
    float ao[1] = {a[1]},       bo[1] = {b[1]};
    float e[4], o[2];
    merge22(ae, be, e); merge11(ao, bo, o);
    c[0] = e[0];
    c[1] = o[0]; c[2] = e[1]; s2(c[1], c[2]);
    c[3] = o[1]; c[4] = e[2]; s2(c[3], c[4]);
    c[5] = e[3];
}
__device__ __forceinline__ void merge44(const float* a, const float* b, float* c) {
    float ae[2] = {a[0], a[2]}, be[2] = {b[0], b[2]};
    float ao[2] = {a[1], a[3]}, bo[2] = {b[1], b[3]};
    float e[4], o[4];
    merge22(ae, be, e); merge22(ao, bo, o);
    c[0] = e[0];
    c[1] = o[0]; c[2] = e[1]; s2(c[1], c[2]);
    c[3] = o[1]; c[4] = e[2]; s2(c[3], c[4]);
    c[5] = o[2]; c[6] = e[3]; s2(c[5], c[6]);
    c[7] = o[3];
}
__device__ __forceinline__ void merge55(const float* a, const float* b, float* c) {
    float ae[3] = {a[0], a[2], a[4]}, be[3] = {b[0], b[2], b[4]};
    float ao[2] = {a[1], a[3]},       bo[2] = {b[1], b[3]};
    float e[6], o[4];
    merge33(ae, be, e); merge22(ao, bo, o);
    c[0] = e[0];
#pragma unroll
    for (int i = 1; i <= 4; ++i) { c[2*i-1] = o[i-1]; c[2*i] = e[i]; s2(c[2*i-1], c[2*i]); }
    c[9] = e[5];
}
// Full merge of two sorted 9s into sorted 18; only c[4..13] are consumed,
// comparators feeding only the ends are dead-coded by ptxas.
__device__ __forceinline__ void merge99(const float* a, const float* b, float* c) {
    float ae[5] = {a[0], a[2], a[4], a[6], a[8]};
    float be[5] = {b[0], b[2], b[4], b[6], b[8]};
    float ao[4] = {a[1], a[3], a[5], a[7]};
    float bo[4] = {b[1], b[3], b[5], b[7]};
    float e[10], o[8];
    merge55(ae, be, e); merge44(ao, bo, o);
    c[0] = e[0];
#pragma unroll
    for (int i = 1; i <= 8; ++i) { c[2*i-1] = o[i-1]; c[2*i] = e[i]; s2(c[2*i-1], c[2*i]); }
    c[17] = e[9];
}

// 10th smallest of sorted X[0..8] ∪ sorted T[0..9]  (== median of the 27-window).
// Closed form: max( T[0], max_i min(X[i], T[9-i]) ).
__device__ __forceinline__ float select10(const float* X, const float* T) {
    float c0 = T[0];
    float c1 = fminf(X[0], T[9]);
    float c2 = fminf(X[1], T[8]);
    float c3 = fminf(X[2], T[7]);
    float c4 = fminf(X[3], T[6]);
    float c5 = fminf(X[4], T[5]);
    float c6 = fminf(X[5], T[4]);
    float c7 = fminf(X[6], T[3]);
    float c8 = fminf(X[7], T[2]);
    float c9 = fminf(X[8], T[1]);
    float m01 = fmaxf(c0, c1), m23 = fmaxf(c2, c3);
    float m45 = fmaxf(c4, c5), m67 = fmaxf(c6, c7);
    float m89 = fmaxf(c8, c9);
    return fmaxf(fmaxf(fmaxf(m01, m23), fmaxf(m45, m67)), m89);
}

// Load the 3x3 (h,w) neighborhood of one D-plane with zero padding.
// Ternary form -> constant immediate LDG offsets + hoisted predicates.
__device__ __forceinline__ void load9(const float* __restrict__ q, float* P,
                                      bool hm, bool hp, bool wm, bool wp) {
    P[0] = (hm && wm) ? __ldg(q - W_DIM - 1) : 0.0f;
    P[1] = (hm)       ? __ldg(q - W_DIM)     : 0.0f;
    P[2] = (hm && wp) ? __ldg(q - W_DIM + 1) : 0.0f;
    P[3] = (wm)       ? __ldg(q - 1)         : 0.0f;
    P[4] =              __ldg(q);
    P[5] = (wp)       ? __ldg(q + 1)         : 0.0f;
    P[6] = (hp && wm) ? __ldg(q + W_DIM - 1) : 0.0f;
    P[7] = (hp)       ? __ldg(q + W_DIM)     : 0.0f;
    P[8] = (hp && wp) ? __ldg(q + W_DIM + 1) : 0.0f;
}

__global__ void __launch_bounds__(128, 10)
median3d_kernel(const float* __restrict__ x, float* __restrict__ y) {
    const int w = blockIdx.x * 128 + threadIdx.x;   // 0..255
    const int h = blockIdx.y;                       // 0..255
    const int d0 = blockIdx.z * D_CHUNK;

    const bool wm = (w > 0), wp = (w < W_DIM - 1);
    const bool hm = (h > 0), hp = (h < H_DIM - 1);

    const float* p0 = x + (size_t)h * W_DIM + w;      // input base at plane 0
    const float* pb = p0 + (size_t)d0 * PLANE;        // input base at plane d0
    float* ob = y + (size_t)d0 * PLANE + (size_t)h * W_DIM + w;  // output base

    float Pm[9], P0[9], P1[9], P2[9];   // sorted planes d-1, d, d+1, d+2
    float c[18];

    // plane d0-1 (zero pad if d0 == 0)
    if (d0 == 0) {
#pragma unroll
        for (int i = 0; i < 9; ++i) Pm[i] = 0.0f;
    } else {
        load9(pb - PLANE, Pm, hm, hp, wm, wp);
        sort9(Pm);
    }
    // plane d0
    load9(pb, P0, hm, hp, wm, wp);
    sort9(P0);

#pragma unroll
    for (int pp = 0; pp < D_CHUNK / 2; ++pp) {
        const int dd = 2 * pp;          // pair (d0+dd, d0+dd+1)

        // plane d0+dd+1 (always exists) — sorted
        load9(pb + (size_t)(dd + 1) * PLANE, P1, hm, hp, wm, wp);
        sort9(P1);

        // plane d0+dd+2 (zero pad if == D_DIM) — sorted
        if (d0 + dd + 2 < D_DIM) {
            load9(pb + (size_t)(dd + 2) * PLANE, P2, hm, hp, wm, wp);
            sort9(P2);
        } else {
#pragma unroll
            for (int i = 0; i < 9; ++i) P2[i] = 0.0f;
        }

        // shared sorted merge of the pair's planes; middle 10 = c[4..13]
        merge99(P0, P1, c);

        // two independent rank selections (high ILP)
        ob[(size_t)dd * PLANE]       = select10(Pm, c + 4);
        ob[(size_t)(dd + 1) * PLANE] = select10(P2, c + 4);

        // slide by 2: Pm <- P1, P0 <- P2 (register-renamed under full unroll)
#pragma unroll
        for (int i = 0; i < 9; ++i) { Pm[i] = P1[i]; P0[i] = P2[i]; }
    }
}

extern "C" void kernel_launch(void* const* d_in, const int* in_sizes, int n_in,
                              void* d_out, int out_size) {
    const float* x = (const float*)d_in[0];
    float* y = (float*)d_out;
    dim3 block(128, 1, 1);
    dim3 grid(W_DIM / 128, H_DIM, D_DIM / D_CHUNK);  // (2, 256, 8) = 4096 CTAs
    median3d_kernel<<<grid, block>>>(x, y);
}